// round 3
// baseline (speedup 1.0000x reference)
#include <cuda_runtime.h>
#include <math_constants.h>
#include <math.h>

#define TOTAL 262144
#define NB 64
#define NA 128
#define ND 128
#define MAXV 4608
#define VQ (MAXV/4)   // 1152 float4 per padded row

// ---- scratch (static __device__ arrays; no allocation allowed) ----
__device__ float g_z[TOTAL];          // logits, then z=exp(logit-max), in place
__device__ float g_max[NB];
__device__ float g_sum[NB];
__device__ float g_coord[NB][3];
__device__ int   g_start[NB];
__device__ float g_padded[NB * MAXV]; // 1.18 MB

__device__ __forceinline__ void atomicMaxFloat(float* addr, float val) {
    int* ia = (int*)addr;
    int old = *ia;
    while (__int_as_float(old) < val) {
        int assumed = old;
        old = atomicCAS(ia, assumed, __float_as_int(val));
        if (old == assumed) break;
    }
}

// K0: init stats + zero padded scratch
__global__ void k_init() {
    int i = blockIdx.x * blockDim.x + threadIdx.x;
    if (i < NB) {
        g_max[i] = -CUDART_INF_F;
        g_sum[i] = 0.0f;
        g_coord[i][0] = 0.0f; g_coord[i][1] = 0.0f; g_coord[i][2] = 0.0f;
        g_start[i] = 0;
    }
    if (i < NB * MAXV) g_padded[i] = 0.0f;
}

// K1: warp-per-node logit = emb[node] . W + b ; per-batch max; segment starts
__global__ void k_logits(const float* __restrict__ emb,
                         const int* __restrict__ bidx,
                         const float* __restrict__ Ww,
                         const float* __restrict__ bw) {
    int gwarp = (blockIdx.x * blockDim.x + threadIdx.x) >> 5;
    int lane  = threadIdx.x & 31;
    if (gwarp >= TOTAL) return;

    float4 e = __ldg(((const float4*)emb) + (size_t)gwarp * 32 + lane);
    float4 w = __ldg(((const float4*)Ww) + lane);
    float dot = e.x * w.x + e.y * w.y + e.z * w.z + e.w * w.w;
    #pragma unroll
    for (int o = 16; o; o >>= 1) dot += __shfl_xor_sync(0xffffffffu, dot, o);

    if (lane == 0) {
        int b = bidx[gwarp];
        float logit = dot + bw[0];
        g_z[gwarp] = logit;
        atomicMaxFloat(&g_max[b], logit);
        // sorted batch_idx -> boundary store is unique (no atomics needed)
        if (gwarp == 0 || bidx[gwarp - 1] != b) g_start[b] = gwarp;
    }
}

// K2: z = exp(logit - max[b]); block-shared reduction of per-batch sums
__global__ void k_expsum(const int* __restrict__ bidx) {
    __shared__ float ssum[NB];
    int t = threadIdx.x;
    if (t < NB) ssum[t] = 0.0f;
    __syncthreads();

    int i = blockIdx.x * blockDim.x + t;
    if (i < TOTAL) {
        int b = bidx[i];
        float m = g_max[b];
        if (!isfinite(m)) m = 0.0f;
        float z = expf(g_z[i] - m);
        g_z[i] = z;
        atomicAdd(&ssum[b], z);
    }
    __syncthreads();
    if (t < NB && ssum[t] != 0.0f) atomicAdd(&g_sum[t], ssum[t]);
}

// K3: w = z/denom; scatter into padded; accumulate per-batch weighted coords
__global__ void k_finalize(const int* __restrict__ bidx,
                           const float* __restrict__ coords) {
    __shared__ float sc[NB][3];
    int t = threadIdx.x;
    if (t < NB) { sc[t][0] = 0.0f; sc[t][1] = 0.0f; sc[t][2] = 0.0f; }
    __syncthreads();

    int i = blockIdx.x * blockDim.x + t;
    if (i < TOTAL) {
        int b = bidx[i];
        float s = g_sum[b];
        float w = g_z[i] / (s > 0.0f ? s : 1.0f);
        int pos = i - g_start[b];
        if (pos > MAXV - 1) pos = MAXV - 1;
        g_padded[b * MAXV + pos] = w;
        atomicAdd(&sc[b][0], w * coords[3 * i + 0]);
        atomicAdd(&sc[b][1], w * coords[3 * i + 1]);
        atomicAdd(&sc[b][2], w * coords[3 * i + 2]);
    }
    __syncthreads();
    if (t < NB) {
        if (sc[t][0] != 0.0f) atomicAdd(&g_coord[t][0], sc[t][0]);
        if (sc[t][1] != 0.0f) atomicAdd(&g_coord[t][1], sc[t][1]);
        if (sc[t][2] != 0.0f) atomicAdd(&g_coord[t][2], sc[t][2]);
    }
}

// K4: predicted_coords[b,a,k] = coord_b[b,k] * mask[b,a]   (mask is int32!)
__global__ void k_coords_out(const int* __restrict__ mask,
                             float* __restrict__ out) {
    int i = blockIdx.x * blockDim.x + threadIdx.x;
    if (i >= NB * NA * 3) return;
    int k = i % 3;
    int ba = i / 3;           // b*NA + a
    int b = ba >> 7;
    out[i] = mask[ba] ? g_coord[b][k] : 0.0f;
}

// K5: attention_weights_all[b,a,v] = padded[b,v] * mask[b,a]  (float4 stores)
__global__ void k_bcast(const int* __restrict__ mask,
                        float4* __restrict__ out) {
    int i = blockIdx.x * blockDim.x + threadIdx.x;   // over NB*NA*VQ = 9,437,184
    if (i >= NB * NA * VQ) return;
    int v4 = i % VQ;
    int ba = i / VQ;          // b*NA + a
    int b = ba >> 7;
    float4 val = make_float4(0.0f, 0.0f, 0.0f, 0.0f);
    if (mask[ba]) val = ((const float4*)g_padded)[b * VQ + v4];
    out[i] = val;
}

extern "C" void kernel_launch(void* const* d_in, const int* in_sizes, int n_in,
                              void* d_out, int out_size) {
    const float* emb    = (const float*)d_in[0];   // [TOTAL, 128] f32
    const float* coords = (const float*)d_in[1];   // [TOTAL, 3]   f32
    const int*   mask   = (const int*)d_in[2];     // [64, 128] bool -> int32
    const int*   bidx   = (const int*)d_in[3];     // [TOTAL] int64 -> int32
    const float* Ww     = (const float*)d_in[4];   // [1, 128] f32
    const float* bw     = (const float*)d_in[5];   // [1] f32
    float* out = (float*)d_out;

    float*  out_coords = out;                       // [64,128,3] = 24576 floats
    float4* out_attn   = (float4*)(out + NB * NA * 3);

    // K0: init (cover NB*MAXV = 294912)
    k_init<<<(NB * MAXV + 255) / 256, 256>>>();

    // K1: 262144 warps, 8 warps/block
    k_logits<<<TOTAL / 8, 256>>>(emb, bidx, Ww, bw);

    // K2: 262144 threads
    k_expsum<<<TOTAL / 256, 256>>>(bidx);

    // K3: 262144 threads
    k_finalize<<<TOTAL / 256, 256>>>(bidx, coords);

    // K4: 24576 threads
    k_coords_out<<<(NB * NA * 3 + 255) / 256, 256>>>(mask, out_coords);

    // K5: 9,437,184 threads
    k_bcast<<<(NB * NA * VQ) / 256, 256>>>(mask, out_attn);
}

// round 4
// speedup vs baseline: 2.7328x; 2.7328x over previous
#include <cuda_runtime.h>
#include <math_constants.h>
#include <math.h>

#define TOTAL 262144
#define NB 64
#define NA 128
#define MAXV 4608
#define VQ (MAXV/4)   // 1152 float4 per padded row

// ---- scratch (static __device__ arrays; no allocation allowed) ----
__device__ float g_z[TOTAL];          // logits, then unused after K2
__device__ float g_coord[NB][3];
__device__ float g_padded[NB * MAXV]; // 1.18 MB, fully written by K2

// K1: warp-per-node logit = emb[node] . W + b  (pure streaming GEMV, no atomics)
__global__ void k_logits(const float* __restrict__ emb,
                         const float* __restrict__ Ww,
                         const float* __restrict__ bw) {
    int gwarp = (blockIdx.x * blockDim.x + threadIdx.x) >> 5;
    int lane  = threadIdx.x & 31;

    float4 e = __ldg(((const float4*)emb) + (size_t)gwarp * 32 + lane);
    float4 w = __ldg(((const float4*)Ww) + lane);
    float dot = fmaf(e.x, w.x, fmaf(e.y, w.y, fmaf(e.z, w.z, e.w * w.w)));
    #pragma unroll
    for (int o = 16; o; o >>= 1) dot += __shfl_xor_sync(0xffffffffu, dot, o);

    if (lane == 0) g_z[gwarp] = dot + bw[0];
}

// K2: one block per batch segment. Binary-search bounds, block-reduce softmax,
// coord accumulation in registers, write full padded row (incl. zero tail).
__global__ __launch_bounds__(1024) void k_segsoftmax(const int* __restrict__ bidx,
                                                     const float* __restrict__ coords) {
    __shared__ float s_z[MAXV];        // 18 KB
    __shared__ float s_red[32];
    __shared__ float s_red4[32][4];
    __shared__ int   s_lo, s_hi;
    __shared__ float s_m, s_denom;

    int b = blockIdx.x;
    int t = threadIdx.x;

    if (t == 0) {
        int lo = 0, hi = TOTAL;                       // lower_bound(bidx, b)
        while (lo < hi) { int mid = (lo + hi) >> 1; if (bidx[mid] < b) lo = mid + 1; else hi = mid; }
        s_lo = lo;
        int lo2 = lo, hi2 = TOTAL;                    // lower_bound(bidx, b+1)
        while (lo2 < hi2) { int mid = (lo2 + hi2) >> 1; if (bidx[mid] < b + 1) lo2 = mid + 1; else hi2 = mid; }
        s_hi = lo2;
    }
    __syncthreads();
    const int lo = s_lo, cnt = s_hi - s_lo;

    // pass 1: stage logits, block max
    float lmax = -CUDART_INF_F;
    for (int i = t; i < cnt; i += 1024) {
        float v = g_z[lo + i];
        s_z[i] = v;
        lmax = fmaxf(lmax, v);
    }
    #pragma unroll
    for (int o = 16; o; o >>= 1) lmax = fmaxf(lmax, __shfl_xor_sync(0xffffffffu, lmax, o));
    if ((t & 31) == 0) s_red[t >> 5] = lmax;
    __syncthreads();
    if (t < 32) {
        float v = s_red[t];
        #pragma unroll
        for (int o = 16; o; o >>= 1) v = fmaxf(v, __shfl_xor_sync(0xffffffffu, v, o));
        if (t == 0) s_m = isfinite(v) ? v : 0.0f;
    }
    __syncthreads();
    const float m = s_m;

    // pass 2: exp, sum, coord accumulation
    float lsum = 0.0f, cx = 0.0f, cy = 0.0f, cz = 0.0f;
    for (int i = t; i < cnt; i += 1024) {
        float z = expf(s_z[i] - m);
        s_z[i] = z;
        lsum += z;
        int g = lo + i;
        cx = fmaf(z, coords[3 * g + 0], cx);
        cy = fmaf(z, coords[3 * g + 1], cy);
        cz = fmaf(z, coords[3 * g + 2], cz);
    }
    #pragma unroll
    for (int o = 16; o; o >>= 1) {
        lsum += __shfl_xor_sync(0xffffffffu, lsum, o);
        cx   += __shfl_xor_sync(0xffffffffu, cx, o);
        cy   += __shfl_xor_sync(0xffffffffu, cy, o);
        cz   += __shfl_xor_sync(0xffffffffu, cz, o);
    }
    if ((t & 31) == 0) {
        s_red4[t >> 5][0] = lsum; s_red4[t >> 5][1] = cx;
        s_red4[t >> 5][2] = cy;   s_red4[t >> 5][3] = cz;
    }
    __syncthreads();
    if (t < 32) {
        float a0 = s_red4[t][0], a1 = s_red4[t][1], a2 = s_red4[t][2], a3 = s_red4[t][3];
        #pragma unroll
        for (int o = 16; o; o >>= 1) {
            a0 += __shfl_xor_sync(0xffffffffu, a0, o);
            a1 += __shfl_xor_sync(0xffffffffu, a1, o);
            a2 += __shfl_xor_sync(0xffffffffu, a2, o);
            a3 += __shfl_xor_sync(0xffffffffu, a3, o);
        }
        if (t == 0) {
            float denom = (a0 > 0.0f) ? a0 : 1.0f;
            s_denom = denom;
            g_coord[b][0] = a1 / denom;
            g_coord[b][1] = a2 / denom;
            g_coord[b][2] = a3 / denom;
        }
    }
    __syncthreads();
    const float inv = 1.0f / s_denom;

    // pass 3: write full padded row (weights + zero tail)
    for (int v = t; v < MAXV; v += 1024)
        g_padded[b * MAXV + v] = (v < cnt) ? s_z[v] * inv : 0.0f;
}

// K3: fused output. grid (3, NB*NA), block 384: exact cover of VQ=1152 float4.
// attention_weights_all[ba, :] = mask[ba] ? padded[b, :] : 0
// predicted_coords[ba, k]      = mask[ba] ? coord[b][k]  : 0  (block x==0 only)
__global__ __launch_bounds__(384) void k_output(const int* __restrict__ mask,
                                                float* __restrict__ out) {
    int ba = blockIdx.y;
    int b  = ba >> 7;
    int mk = __ldg(&mask[ba]);

    float4* out_attn = (float4*)(out + NB * NA * 3);
    int v4 = blockIdx.x * 384 + threadIdx.x;       // 0..1151

    float4 val = make_float4(0.0f, 0.0f, 0.0f, 0.0f);
    if (mk) val = ((const float4*)g_padded)[b * VQ + v4];
    out_attn[(size_t)ba * VQ + v4] = val;

    if (blockIdx.x == 0 && threadIdx.x < 3)
        out[ba * 3 + threadIdx.x] = mk ? g_coord[b][threadIdx.x] : 0.0f;
}

extern "C" void kernel_launch(void* const* d_in, const int* in_sizes, int n_in,
                              void* d_out, int out_size) {
    const float* emb    = (const float*)d_in[0];   // [TOTAL, 128] f32
    const float* coords = (const float*)d_in[1];   // [TOTAL, 3]   f32
    const int*   mask   = (const int*)d_in[2];     // [64, 128] bool -> int32
    const int*   bidx   = (const int*)d_in[3];     // [TOTAL] int64 -> int32 (sorted)
    const float* Ww     = (const float*)d_in[4];   // [1, 128] f32
    const float* bw     = (const float*)d_in[5];   // [1] f32
    float* out = (float*)d_out;

    // K1: 262144 warps, 8 warps/block
    k_logits<<<TOTAL / 8, 256>>>(emb, Ww, bw);

    // K2: one block per batch
    k_segsoftmax<<<NB, 1024>>>(bidx, coords);

    // K3: exact-cover broadcast + coords
    dim3 g3(3, NB * NA);
    k_output<<<g3, 384>>>(mask, out);
}

// round 5
// speedup vs baseline: 3.3299x; 1.2185x over previous
#include <cuda_runtime.h>
#include <math_constants.h>
#include <math.h>

#define TOTAL 262144
#define NB 64
#define NA 128
#define MAXV 4608
#define VQ (MAXV/4)   // 1152 float4 per padded row

// ---- scratch (static __device__ arrays; no allocation allowed) ----
__device__ float g_z[TOTAL];          // logits (written as float4 groups)
__device__ float g_coord[NB][3];
__device__ float g_padded[NB * MAXV]; // 1.18 MB, fully written by K2

// K1: each warp computes 4 row-dots (MLP=4 per lane), stores 4 logits as one float4.
__global__ __launch_bounds__(256) void k_logits(const float* __restrict__ emb,
                                                const float* __restrict__ Ww,
                                                const float* __restrict__ bw) {
    int warp = (blockIdx.x * blockDim.x + threadIdx.x) >> 5;   // 0..65535
    int lane = threadIdx.x & 31;
    size_t base = (size_t)warp * 4 * 32;                        // float4 index of row 4*warp

    const float4* emb4 = (const float4*)emb;
    float4 w = __ldg(((const float4*)Ww) + lane);

    // 4 independent loads in flight
    float4 e0 = __ldg(emb4 + base + 0 * 32 + lane);
    float4 e1 = __ldg(emb4 + base + 1 * 32 + lane);
    float4 e2 = __ldg(emb4 + base + 2 * 32 + lane);
    float4 e3 = __ldg(emb4 + base + 3 * 32 + lane);

    float d0 = fmaf(e0.x, w.x, fmaf(e0.y, w.y, fmaf(e0.z, w.z, e0.w * w.w)));
    float d1 = fmaf(e1.x, w.x, fmaf(e1.y, w.y, fmaf(e1.z, w.z, e1.w * w.w)));
    float d2 = fmaf(e2.x, w.x, fmaf(e2.y, w.y, fmaf(e2.z, w.z, e2.w * w.w)));
    float d3 = fmaf(e3.x, w.x, fmaf(e3.y, w.y, fmaf(e3.z, w.z, e3.w * w.w)));

    #pragma unroll
    for (int o = 16; o; o >>= 1) {
        d0 += __shfl_xor_sync(0xffffffffu, d0, o);
        d1 += __shfl_xor_sync(0xffffffffu, d1, o);
        d2 += __shfl_xor_sync(0xffffffffu, d2, o);
        d3 += __shfl_xor_sync(0xffffffffu, d3, o);
    }
    if (lane == 0) {
        float bias = bw[0];
        ((float4*)g_z)[warp] = make_float4(d0 + bias, d1 + bias, d2 + bias, d3 + bias);
    }
}

// K2: one block per batch segment. Binary-search bounds, block-reduce softmax,
// coord accumulation in registers, write full padded row (incl. zero tail).
__global__ __launch_bounds__(1024) void k_segsoftmax(const int* __restrict__ bidx,
                                                     const float* __restrict__ coords) {
    __shared__ float s_z[MAXV];        // 18 KB
    __shared__ float s_red[32];
    __shared__ float s_red4[32][4];
    __shared__ int   s_lo, s_hi;
    __shared__ float s_m, s_denom;

    int b = blockIdx.x;
    int t = threadIdx.x;

    if (t == 0) {
        int lo = 0, hi = TOTAL;                       // lower_bound(bidx, b)
        while (lo < hi) { int mid = (lo + hi) >> 1; if (bidx[mid] < b) lo = mid + 1; else hi = mid; }
        s_lo = lo;
        int lo2 = lo, hi2 = TOTAL;                    // lower_bound(bidx, b+1)
        while (lo2 < hi2) { int mid = (lo2 + hi2) >> 1; if (bidx[mid] < b + 1) lo2 = mid + 1; else hi2 = mid; }
        s_hi = lo2;
    }
    __syncthreads();
    const int lo = s_lo, cnt = s_hi - s_lo;

    // pass 1: stage logits, block max
    float lmax = -CUDART_INF_F;
    for (int i = t; i < cnt; i += 1024) {
        float v = g_z[lo + i];
        s_z[i] = v;
        lmax = fmaxf(lmax, v);
    }
    #pragma unroll
    for (int o = 16; o; o >>= 1) lmax = fmaxf(lmax, __shfl_xor_sync(0xffffffffu, lmax, o));
    if ((t & 31) == 0) s_red[t >> 5] = lmax;
    __syncthreads();
    if (t < 32) {
        float v = s_red[t];
        #pragma unroll
        for (int o = 16; o; o >>= 1) v = fmaxf(v, __shfl_xor_sync(0xffffffffu, v, o));
        if (t == 0) s_m = isfinite(v) ? v : 0.0f;
    }
    __syncthreads();
    const float m = s_m;

    // pass 2: exp, sum, coord accumulation
    float lsum = 0.0f, cx = 0.0f, cy = 0.0f, cz = 0.0f;
    for (int i = t; i < cnt; i += 1024) {
        float z = expf(s_z[i] - m);
        s_z[i] = z;
        lsum += z;
        int g = lo + i;
        cx = fmaf(z, coords[3 * g + 0], cx);
        cy = fmaf(z, coords[3 * g + 1], cy);
        cz = fmaf(z, coords[3 * g + 2], cz);
    }
    #pragma unroll
    for (int o = 16; o; o >>= 1) {
        lsum += __shfl_xor_sync(0xffffffffu, lsum, o);
        cx   += __shfl_xor_sync(0xffffffffu, cx, o);
        cy   += __shfl_xor_sync(0xffffffffu, cy, o);
        cz   += __shfl_xor_sync(0xffffffffu, cz, o);
    }
    if ((t & 31) == 0) {
        s_red4[t >> 5][0] = lsum; s_red4[t >> 5][1] = cx;
        s_red4[t >> 5][2] = cy;   s_red4[t >> 5][3] = cz;
    }
    __syncthreads();
    if (t < 32) {
        float a0 = s_red4[t][0], a1 = s_red4[t][1], a2 = s_red4[t][2], a3 = s_red4[t][3];
        #pragma unroll
        for (int o = 16; o; o >>= 1) {
            a0 += __shfl_xor_sync(0xffffffffu, a0, o);
            a1 += __shfl_xor_sync(0xffffffffu, a1, o);
            a2 += __shfl_xor_sync(0xffffffffu, a2, o);
            a3 += __shfl_xor_sync(0xffffffffu, a3, o);
        }
        if (t == 0) {
            float denom = (a0 > 0.0f) ? a0 : 1.0f;
            s_denom = denom;
            g_coord[b][0] = a1 / denom;
            g_coord[b][1] = a2 / denom;
            g_coord[b][2] = a3 / denom;
        }
    }
    __syncthreads();
    const float inv = 1.0f / s_denom;

    // pass 3: write full padded row (weights + zero tail)
    for (int v = t; v < MAXV; v += 1024)
        g_padded[b * MAXV + v] = (v < cnt) ? s_z[v] * inv : 0.0f;
}

// K3: one block per (b, a) row. Each thread writes 3 independent float4
// (384 * 3 = 1152 = VQ exact cover). Coords fused.
__global__ __launch_bounds__(384) void k_output(const int* __restrict__ mask,
                                                float* __restrict__ out) {
    int ba = blockIdx.x;
    int b  = ba >> 7;
    int mk = __ldg(&mask[ba]);

    float4* out_row = ((float4*)(out + NB * NA * 3)) + (size_t)ba * VQ;
    const float4* pad_row = ((const float4*)g_padded) + b * VQ;
    int t = threadIdx.x;

    if (mk) {
        float4 v0 = pad_row[t];
        float4 v1 = pad_row[t + 384];
        float4 v2 = pad_row[t + 768];
        out_row[t]       = v0;
        out_row[t + 384] = v1;
        out_row[t + 768] = v2;
        if (t < 3) out[ba * 3 + t] = g_coord[b][t];
    } else {
        float4 z = make_float4(0.0f, 0.0f, 0.0f, 0.0f);
        out_row[t]       = z;
        out_row[t + 384] = z;
        out_row[t + 768] = z;
        if (t < 3) out[ba * 3 + t] = 0.0f;
    }
}

extern "C" void kernel_launch(void* const* d_in, const int* in_sizes, int n_in,
                              void* d_out, int out_size) {
    const float* emb    = (const float*)d_in[0];   // [TOTAL, 128] f32
    const float* coords = (const float*)d_in[1];   // [TOTAL, 3]   f32
    const int*   mask   = (const int*)d_in[2];     // [64, 128] bool -> int32
    const int*   bidx   = (const int*)d_in[3];     // [TOTAL] int64 -> int32 (sorted)
    const float* Ww     = (const float*)d_in[4];   // [1, 128] f32
    const float* bw     = (const float*)d_in[5];   // [1] f32
    float* out = (float*)d_out;

    // K1: 65536 warps (4 rows each), 8 warps/block -> 8192 blocks
    k_logits<<<TOTAL / 32, 256>>>(emb, Ww, bw);

    // K2: one block per batch
    k_segsoftmax<<<NB, 1024>>>(bidx, coords);

    // K3: one block per (b,a) row
    k_output<<<NB * NA, 384>>>(mask, out);
}